// round 2
// baseline (speedup 1.0000x reference)
#include <cuda_runtime.h>

// Problem constants
#define IMG_H 512
#define IMG_W 512
#define NBATCH 32
#define TILE 32

// Global accumulators: [0] = sum((out-g2)^2 + 2*(out-g1)^2), [1] = weighted wavelet sum
__device__ double g_acc[2];

__global__ void init_acc_kernel() {
    g_acc[0] = 0.0;
    g_acc[1] = 0.0;
}

__global__ void __launch_bounds__(256) fused_loss_kernel(
    const float* __restrict__ noisy,   // (32,1,512,512)
    const float* __restrict__ weight)  // (1,1,3,3)
{
    const int tx0 = blockIdx.x * TILE;   // tile col origin in [0,512)
    const int ty0 = blockIdx.y * TILE;   // tile row origin
    const int b   = blockIdx.z;
    const float* img = noisy + (size_t)b * IMG_H * IMG_W;

    __shared__ float sp0[18][18];    // p0 patch (even rows/cols), clamped
    __shared__ float sp3[18][18];    // p3 patch (odd rows/cols), clamped
    __shared__ float sg1[34][36];    // g1 with 1-px halo (zero outside image, conv pad)
    __shared__ float sout[32][33];   // clipped conv output tile
    __shared__ float sll1[16][17];   // Haar level-1 LL
    __shared__ float sll2[8][9];     // Haar level-2 LL
    __shared__ float sw[9];
    __shared__ double red[2][8];

    const int t  = threadIdx.x;
    const int k0 = ty0 >> 1;   // p0/p3 row origin (before -1 halo)
    const int l0 = tx0 >> 1;

    if (t < 9) sw[t] = weight[t];

    // ---- load p0 / p3 18x18 patches (clamped indices == jax edge renorm) ----
    for (int idx = t; idx < 18 * 18; idx += 256) {
        int dy = idx / 18, dx = idx % 18;
        int k = min(max(k0 - 1 + dy, 0), (IMG_H / 2) - 1);
        int l = min(max(l0 - 1 + dx, 0), (IMG_W / 2) - 1);
        sp0[dy][dx] = img[(2 * k) * IMG_W + 2 * l];
        sp3[dy][dx] = img[(2 * k + 1) * IMG_W + 2 * l + 1];
    }
    __syncthreads();

    // ---- build g1 halo 34x34 (bilinear upsample of p0; 0 outside image for conv pad) ----
    for (int idx = t; idx < 34 * 34; idx += 256) {
        int dy = idx / 34, dx = idx % 34;
        int gi = ty0 - 1 + dy, gj = tx0 - 1 + dx;
        float v = 0.0f;
        if (gi >= 0 && gi < IMG_H && gj >= 0 && gj < IMG_W) {
            // sample coord = 0.5*i - 0.25 -> taps with weights {0.25, 0.75}
            int ty_, tx_; float wy0, wx0;
            if (gi & 1) { ty_ = gi >> 1;        wy0 = 0.75f; }
            else        { ty_ = (gi >> 1) - 1;  wy0 = 0.25f; }
            if (gj & 1) { tx_ = gj >> 1;        wx0 = 0.75f; }
            else        { tx_ = (gj >> 1) - 1;  wx0 = 0.25f; }
            int sy = ty_ - (k0 - 1), sx = tx_ - (l0 - 1);
            float a  = sp0[sy][sx],     bb = sp0[sy][sx + 1];
            float cc = sp0[sy + 1][sx], dd = sp0[sy + 1][sx + 1];
            v = wy0 * (wx0 * a + (1.0f - wx0) * bb)
              + (1.0f - wy0) * (wx0 * cc + (1.0f - wx0) * dd);
        }
        sg1[dy][dx] = v;
    }
    __syncthreads();

    // ---- conv3x3 (cross-correlation) + clip + N2N accumulation ----
    float accA = 0.0f;
    const float w00 = sw[0], w01 = sw[1], w02 = sw[2];
    const float w10 = sw[3], w11 = sw[4], w12 = sw[5];
    const float w20 = sw[6], w21 = sw[7], w22 = sw[8];
    #pragma unroll
    for (int q = 0; q < 4; q++) {
        int ly = (t >> 5) + (q << 3);   // row within tile
        int lx = t & 31;                // col within tile
        float s =
            sg1[ly + 0][lx + 0] * w00 + sg1[ly + 0][lx + 1] * w01 + sg1[ly + 0][lx + 2] * w02 +
            sg1[ly + 1][lx + 0] * w10 + sg1[ly + 1][lx + 1] * w11 + sg1[ly + 1][lx + 2] * w12 +
            sg1[ly + 2][lx + 0] * w20 + sg1[ly + 2][lx + 1] * w21 + sg1[ly + 2][lx + 2] * w22;
        float o = fminf(fmaxf(s, 0.0f), 1.0f);
        sout[ly][lx] = o;

        float g1v = sg1[ly + 1][lx + 1];

        // g2 bilinear from p3 (same tap math)
        int gi = ty0 + ly, gj = tx0 + lx;
        int ty_, tx_; float wy0, wx0;
        if (gi & 1) { ty_ = gi >> 1;        wy0 = 0.75f; }
        else        { ty_ = (gi >> 1) - 1;  wy0 = 0.25f; }
        if (gj & 1) { tx_ = gj >> 1;        wx0 = 0.75f; }
        else        { tx_ = (gj >> 1) - 1;  wx0 = 0.25f; }
        int sy = ty_ - (k0 - 1), sx = tx_ - (l0 - 1);
        float g2v = wy0 * (wx0 * sp3[sy][sx] + (1.0f - wx0) * sp3[sy][sx + 1])
                  + (1.0f - wy0) * (wx0 * sp3[sy + 1][sx] + (1.0f - wx0) * sp3[sy + 1][sx + 1]);

        float d1 = o - g2v;
        float d2 = o - g1v;
        accA += d1 * d1 + 2.0f * d2 * d2;   // rec + GAMMA*reg (GAMMA=2)
    }
    __syncthreads();

    // ---- Haar wavelet sparsity (local: 32x32 tile is 8-aligned) ----
    const float T = 50.0f / 255.0f;
    float s1 = 0.0f, s2 = 0.0f, s3 = 0.0f;
    {   // level 1: 16x16 outputs, one per thread
        int r = t >> 4, c = t & 15;
        float a  = sout[2 * r][2 * c],     bb = sout[2 * r][2 * c + 1];
        float cc = sout[2 * r + 1][2 * c], dd = sout[2 * r + 1][2 * c + 1];
        float ll = (a + bb + cc + dd) * 0.5f;
        float lh = (a - bb + cc - dd) * 0.5f;
        float hl = (a + bb - cc - dd) * 0.5f;
        float hh = (a - bb - cc + dd) * 0.5f;
        float thr = T * 0.25f;   // level_idx=3 -> T/4
        s1 = fminf(fabsf(lh), thr) + fminf(fabsf(hl), thr) + fminf(fabsf(hh), thr);
        sll1[r][c] = ll;
    }
    __syncthreads();
    if (t < 64) {   // level 2: 8x8 outputs
        int r = t >> 3, c = t & 7;
        float a  = sll1[2 * r][2 * c],     bb = sll1[2 * r][2 * c + 1];
        float cc = sll1[2 * r + 1][2 * c], dd = sll1[2 * r + 1][2 * c + 1];
        float ll = (a + bb + cc + dd) * 0.5f;
        float lh = (a - bb + cc - dd) * 0.5f;
        float hl = (a + bb - cc - dd) * 0.5f;
        float hh = (a - bb - cc + dd) * 0.5f;
        float thr = T * 0.5f;    // level_idx=2 -> T/2
        s2 = fminf(fabsf(lh), thr) + fminf(fabsf(hl), thr) + fminf(fabsf(hh), thr);
        sll2[r][c] = ll;
    }
    __syncthreads();
    if (t < 16) {   // level 3: 4x4 outputs
        int r = t >> 2, c = t & 3;
        float a  = sll2[2 * r][2 * c],     bb = sll2[2 * r][2 * c + 1];
        float cc = sll2[2 * r + 1][2 * c], dd = sll2[2 * r + 1][2 * c + 1];
        float lh = (a - bb + cc - dd) * 0.5f;
        float hl = (a + bb - cc - dd) * 0.5f;
        float hh = (a - bb - cc + dd) * 0.5f;
        float thr = T;           // level_idx=1 -> T
        s3 = fminf(fabsf(lh), thr) + fminf(fabsf(hl), thr) + fminf(fabsf(hh), thr);
    }

    // per-element weights: w_j / (3 * N_j)
    // N1 = 32*256*256, N2 = 32*128*128, N3 = 32*64*64
    const double c1 = (1.0 / 3.0) / (3.0 * 2097152.0);
    const double c2 = (1.0 / 2.0) / (3.0 * 524288.0);
    const double c3 = 1.0 / (3.0 * 131072.0);

    double myA = (double)accA;
    double myW = c1 * (double)s1 + c2 * (double)s2 + c3 * (double)s3;

    // ---- block reduction (8 warps) ----
    #pragma unroll
    for (int off = 16; off > 0; off >>= 1) {
        myA += __shfl_down_sync(0xffffffff, myA, off);
        myW += __shfl_down_sync(0xffffffff, myW, off);
    }
    int warp = t >> 5, lane = t & 31;
    if (lane == 0) { red[0][warp] = myA; red[1][warp] = myW; }
    __syncthreads();
    if (t == 0) {
        double A = 0.0, Wv = 0.0;
        #pragma unroll
        for (int i = 0; i < 8; i++) { A += red[0][i]; Wv += red[1][i]; }
        atomicAdd(&g_acc[0], A);
        atomicAdd(&g_acc[1], Wv);
    }
}

__global__ void finalize_kernel(float* __restrict__ out) {
    // n2n mean over 32*512*512 elements + 0.05 * wavelet
    out[0] = (float)(g_acc[0] / 8388608.0 + 0.05 * g_acc[1]);
}

extern "C" void kernel_launch(void* const* d_in, const int* in_sizes, int n_in,
                              void* d_out, int out_size) {
    const float* noisy  = (const float*)d_in[0];
    const float* weight = (const float*)d_in[1];
    float* out = (float*)d_out;

    init_acc_kernel<<<1, 1>>>();
    dim3 grid(IMG_W / TILE, IMG_H / TILE, NBATCH);   // 16 x 16 x 32
    fused_loss_kernel<<<grid, 256>>>(noisy, weight);
    finalize_kernel<<<1, 1>>>(out);
}

// round 3
// speedup vs baseline: 1.9789x; 1.9789x over previous
#include <cuda_runtime.h>

#define IMG_H 512
#define IMG_W 512
#define NBATCH 32
#define TILE 32
#define NBLOCKS (16 * 16 * 32)   // 8192

// Per-block partial sums: .x = n2n sum, .y = weighted wavelet sum.
// Overwritten by every block on every launch -> no init kernel needed.
__device__ double2 g_part[NBLOCKS];

__global__ void __launch_bounds__(256) fused_loss_kernel(
    const float* __restrict__ noisy,   // (32,1,512,512)
    const float* __restrict__ weight)  // (1,1,3,3)
{
    const int tx0 = blockIdx.x * TILE;
    const int ty0 = blockIdx.y * TILE;
    const int b   = blockIdx.z;
    const float* img = noisy + (size_t)b * IMG_H * IMG_W;

    __shared__ float sp0[18][20];    // even-row/even-col sub-image patch (clamped)
    __shared__ float sp3[18][20];    // odd-row/odd-col sub-image patch (clamped)
    __shared__ float sll1[16][17];   // Haar level-1 LL
    __shared__ float sll2[8][9];     // Haar level-2 LL
    __shared__ float sw[9];
    __shared__ double red[2][8];

    const int t  = threadIdx.x;
    const int k0 = ty0 >> 1;
    const int l0 = tx0 >> 1;

    if (t < 9) sw[t] = weight[t];

    // ---- load 18x18 p0/p3 patches (index clamp == jax resize edge renorm) ----
    #pragma unroll
    for (int ii = 0; ii < 2; ii++) {
        int idx = t + ii * 256;
        if (idx < 18 * 18) {
            int dy = idx / 18, dx = idx % 18;
            int k = min(max(k0 - 1 + dy, 0), (IMG_H / 2) - 1);
            int l = min(max(l0 - 1 + dx, 0), (IMG_W / 2) - 1);
            sp0[dy][dx] = img[(2 * k) * IMG_W + 2 * l];
            sp3[dy][dx] = img[(2 * k + 1) * IMG_W + 2 * l + 1];
        }
    }
    __syncthreads();

    // ---- per-thread 2x2 output quad, fully register-resident ----
    const int qy = t >> 4;           // 0..15
    const int qx = t & 15;           // 0..15
    const int gi0 = ty0 + 2 * qy;    // even global row of quad
    const int gj0 = tx0 + 2 * qx;    // even global col of quad

    // p0 3x3 window: patch rows qy..qy+2, cols qx..qx+2
    float P00 = sp0[qy    ][qx], P01 = sp0[qy    ][qx + 1], P02 = sp0[qy    ][qx + 2];
    float P10 = sp0[qy + 1][qx], P11 = sp0[qy + 1][qx + 1], P12 = sp0[qy + 1][qx + 2];
    float P20 = sp0[qy + 2][qx], P21 = sp0[qy + 2][qx + 1], P22 = sp0[qy + 2][qx + 2];

    // row-interpolated g1 rows (gi0-1, gi0, gi0+1, gi0+2) at 3 p0 columns
    float RA0 = 0.75f * P00 + 0.25f * P10, RA1 = 0.75f * P01 + 0.25f * P11, RA2 = 0.75f * P02 + 0.25f * P12;
    float RB0 = 0.25f * P00 + 0.75f * P10, RB1 = 0.25f * P01 + 0.75f * P11, RB2 = 0.25f * P02 + 0.75f * P12;
    float RC0 = 0.75f * P10 + 0.25f * P20, RC1 = 0.75f * P11 + 0.25f * P21, RC2 = 0.75f * P12 + 0.25f * P22;
    float RD0 = 0.25f * P10 + 0.75f * P20, RD1 = 0.25f * P11 + 0.75f * P21, RD2 = 0.25f * P12 + 0.75f * P22;

    // conv zero-pad masks (only outermost g1 row/col can be outside image)
    float mr0 = (gi0 > 0)           ? 1.0f : 0.0f;
    float mr3 = (gi0 + 2 < IMG_H)   ? 1.0f : 0.0f;
    float mc0 = (gj0 > 0)           ? 1.0f : 0.0f;
    float mc3 = (gj0 + 2 < IMG_W)   ? 1.0f : 0.0f;

    // column-interp -> 4x4 g1 window, masked
    float G[4][4];
    {
        float r0[3] = {RA0, RA1, RA2}, r1[3] = {RB0, RB1, RB2};
        float r2[3] = {RC0, RC1, RC2}, r3[3] = {RD0, RD1, RD2};
        float* rows[4] = {r0, r1, r2, r3};
        #pragma unroll
        for (int r = 0; r < 4; r++) {
            float* R = rows[r];
            G[r][0] = 0.75f * R[0] + 0.25f * R[1];
            G[r][1] = 0.25f * R[0] + 0.75f * R[1];
            G[r][2] = 0.75f * R[1] + 0.25f * R[2];
            G[r][3] = 0.25f * R[1] + 0.75f * R[2];
        }
        #pragma unroll
        for (int c = 0; c < 4; c++) { G[0][c] *= mr0; G[3][c] *= mr3; }
        #pragma unroll
        for (int r = 0; r < 4; r++) { G[r][0] *= mc0; G[r][3] *= mc3; }
    }

    // 3x3 conv (cross-correlation) on the quad + clip
    const float w00 = sw[0], w01 = sw[1], w02 = sw[2];
    const float w10 = sw[3], w11 = sw[4], w12 = sw[5];
    const float w20 = sw[6], w21 = sw[7], w22 = sw[8];
    float o[2][2];
    #pragma unroll
    for (int dy = 0; dy < 2; dy++) {
        #pragma unroll
        for (int dx = 0; dx < 2; dx++) {
            float s = G[dy    ][dx] * w00 + G[dy    ][dx + 1] * w01 + G[dy    ][dx + 2] * w02
                    + G[dy + 1][dx] * w10 + G[dy + 1][dx + 1] * w11 + G[dy + 1][dx + 2] * w12
                    + G[dy + 2][dx] * w20 + G[dy + 2][dx + 1] * w21 + G[dy + 2][dx + 2] * w22;
            o[dy][dx] = fminf(fmaxf(s, 0.0f), 1.0f);
        }
    }

    // g2 quad from p3 3x3 window
    float Q00 = sp3[qy    ][qx], Q01 = sp3[qy    ][qx + 1], Q02 = sp3[qy    ][qx + 2];
    float Q10 = sp3[qy + 1][qx], Q11 = sp3[qy + 1][qx + 1], Q12 = sp3[qy + 1][qx + 2];
    float Q20 = sp3[qy + 2][qx], Q21 = sp3[qy + 2][qx + 1], Q22 = sp3[qy + 2][qx + 2];
    float SA0 = 0.25f * Q00 + 0.75f * Q10, SA1 = 0.25f * Q01 + 0.75f * Q11, SA2 = 0.25f * Q02 + 0.75f * Q12;
    float SB0 = 0.75f * Q10 + 0.25f * Q20, SB1 = 0.75f * Q11 + 0.25f * Q21, SB2 = 0.75f * Q12 + 0.25f * Q22;
    float g2q[2][2];
    g2q[0][0] = 0.75f * SA0 + 0.25f * SA1;  g2q[0][1] = 0.25f * SA0 + 0.75f * SA1;
    // careful: cols gj0 (even) -> 0.25/0.75 over (l-1,l); gj0+1 (odd) -> 0.75/0.25 over (l,l+1)
    g2q[0][0] = 0.25f * SA0 + 0.75f * SA1;  g2q[0][1] = 0.75f * SA1 + 0.25f * SA2;
    g2q[1][0] = 0.25f * SB0 + 0.75f * SB1;  g2q[1][1] = 0.75f * SB1 + 0.25f * SB2;

    // N2N: (out-g2)^2 + 2*(out-g1)^2 ; g1 at quad = G[1+dy][1+dx]
    float accA = 0.0f;
    #pragma unroll
    for (int dy = 0; dy < 2; dy++) {
        #pragma unroll
        for (int dx = 0; dx < 2; dx++) {
            float d1 = o[dy][dx] - g2q[dy][dx];
            float d2 = o[dy][dx] - G[1 + dy][1 + dx];
            accA += d1 * d1 + 2.0f * d2 * d2;
        }
    }

    // ---- Haar level 1 directly from the quad (registers) ----
    const float T = 50.0f / 255.0f;
    float s1, s2 = 0.0f, s3 = 0.0f;
    {
        float a = o[0][0], bb = o[0][1], cc = o[1][0], dd = o[1][1];
        float ll = (a + bb + cc + dd) * 0.5f;
        float lh = (a - bb + cc - dd) * 0.5f;
        float hl = (a + bb - cc - dd) * 0.5f;
        float hh = (a - bb - cc + dd) * 0.5f;
        float thr = T * 0.25f;
        s1 = fminf(fabsf(lh), thr) + fminf(fabsf(hl), thr) + fminf(fabsf(hh), thr);
        sll1[qy][qx] = ll;
    }
    __syncthreads();
    if (t < 64) {   // level 2: 8x8
        int r = t >> 3, c = t & 7;
        float a  = sll1[2 * r][2 * c],     bb = sll1[2 * r][2 * c + 1];
        float cc = sll1[2 * r + 1][2 * c], dd = sll1[2 * r + 1][2 * c + 1];
        float ll = (a + bb + cc + dd) * 0.5f;
        float lh = (a - bb + cc - dd) * 0.5f;
        float hl = (a + bb - cc - dd) * 0.5f;
        float hh = (a - bb - cc + dd) * 0.5f;
        float thr = T * 0.5f;
        s2 = fminf(fabsf(lh), thr) + fminf(fabsf(hl), thr) + fminf(fabsf(hh), thr);
        sll2[r][c] = ll;
    }
    __syncthreads();
    if (t < 16) {   // level 3: 4x4
        int r = t >> 2, c = t & 3;
        float a  = sll2[2 * r][2 * c],     bb = sll2[2 * r][2 * c + 1];
        float cc = sll2[2 * r + 1][2 * c], dd = sll2[2 * r + 1][2 * c + 1];
        float lh = (a - bb + cc - dd) * 0.5f;
        float hl = (a + bb - cc - dd) * 0.5f;
        float hh = (a - bb - cc + dd) * 0.5f;
        s3 = fminf(fabsf(lh), T) + fminf(fabsf(hl), T) + fminf(fabsf(hh), T);
    }

    // per-element wavelet weights: w_j / (3 * N_j)
    const float c1 = (float)((1.0 / 3.0) / (3.0 * 2097152.0));
    const float c2 = (float)((1.0 / 2.0) / (3.0 * 524288.0));
    const float c3 = (float)(1.0 / (3.0 * 131072.0));
    float myW = c1 * s1 + c2 * s2 + c3 * s3;

    // ---- reduction: float within warp, double across warps ----
    float mA = accA, mW = myW;
    #pragma unroll
    for (int off = 16; off > 0; off >>= 1) {
        mA += __shfl_down_sync(0xffffffff, mA, off);
        mW += __shfl_down_sync(0xffffffff, mW, off);
    }
    int warp = t >> 5, lane = t & 31;
    if (lane == 0) { red[0][warp] = (double)mA; red[1][warp] = (double)mW; }
    __syncthreads();
    if (t == 0) {
        double A = 0.0, Wv = 0.0;
        #pragma unroll
        for (int i = 0; i < 8; i++) { A += red[0][i]; Wv += red[1][i]; }
        int bid = (blockIdx.z * gridDim.y + blockIdx.y) * gridDim.x + blockIdx.x;
        g_part[bid] = make_double2(A, Wv);
    }
}

__global__ void __launch_bounds__(1024) finalize_kernel(float* __restrict__ out) {
    __shared__ double red[2][32];
    int t = threadIdx.x;
    double A = 0.0, Wv = 0.0;
    #pragma unroll
    for (int i = t; i < NBLOCKS; i += 1024) {
        double2 p = g_part[i];
        A += p.x; Wv += p.y;
    }
    #pragma unroll
    for (int off = 16; off > 0; off >>= 1) {
        A  += __shfl_down_sync(0xffffffff, A, off);
        Wv += __shfl_down_sync(0xffffffff, Wv, off);
    }
    int warp = t >> 5, lane = t & 31;
    if (lane == 0) { red[0][warp] = A; red[1][warp] = Wv; }
    __syncthreads();
    if (warp == 0) {
        A  = red[0][lane];
        Wv = red[1][lane];
        #pragma unroll
        for (int off = 16; off > 0; off >>= 1) {
            A  += __shfl_down_sync(0xffffffff, A, off);
            Wv += __shfl_down_sync(0xffffffff, Wv, off);
        }
        if (t == 0)
            out[0] = (float)(A / 8388608.0 + 0.05 * Wv);
    }
}

extern "C" void kernel_launch(void* const* d_in, const int* in_sizes, int n_in,
                              void* d_out, int out_size) {
    const float* noisy  = (const float*)d_in[0];
    const float* weight = (const float*)d_in[1];
    float* out = (float*)d_out;

    dim3 grid(IMG_W / TILE, IMG_H / TILE, NBATCH);   // 16 x 16 x 32
    fused_loss_kernel<<<grid, 256>>>(noisy, weight);
    finalize_kernel<<<1, 1024>>>(out);
}

// round 4
// speedup vs baseline: 2.9106x; 1.4708x over previous
#include <cuda_runtime.h>

#define IMG_H 512
#define IMG_W 512
#define NBATCH 32
#define TILE 64
#define NBLOCKS (8 * 8 * 32)   // 2048

// Per-block partial sums: .x = n2n sum, .y = weighted wavelet sum.
__device__ double2 g_part[NBLOCKS];
// Monotonic ticket counter; (old % NBLOCKS == NBLOCKS-1) -> last block of this launch.
__device__ unsigned int g_ticket = 0;

__global__ void __launch_bounds__(256) fused_loss_kernel(
    const float* __restrict__ noisy,   // (32,1,512,512)
    const float* __restrict__ weight,  // (1,1,3,3)
    float* __restrict__ out)
{
    const int tx0 = blockIdx.x * TILE;
    const int ty0 = blockIdx.y * TILE;
    const int b   = blockIdx.z;
    const float* img = noisy + (size_t)b * IMG_H * IMG_W;

    __shared__ float sp0[34][36];    // even-row/even-col sub-image patch (clamped), halo 1
    __shared__ float sp3[34][36];    // odd-row/odd-col sub-image patch (clamped), halo 1
    __shared__ float sll1[32][33];   // Haar level-1 LL (32x32)
    __shared__ float sll2[16][17];   // Haar level-2 LL (16x16)
    __shared__ double red[2][8];
    __shared__ bool isLast;

    const int t  = threadIdx.x;
    const int k0 = ty0 >> 1;
    const int l0 = tx0 >> 1;

    // conv weights (uniform broadcast through L1)
    const float w00 = __ldg(weight + 0), w01 = __ldg(weight + 1), w02 = __ldg(weight + 2);
    const float w10 = __ldg(weight + 3), w11 = __ldg(weight + 4), w12 = __ldg(weight + 5);
    const float w20 = __ldg(weight + 6), w21 = __ldg(weight + 7), w22 = __ldg(weight + 8);

    // ---- load 34x34 p0/p3 patches (index clamp == jax resize edge renorm) ----
    #pragma unroll
    for (int ii = 0; ii < 5; ii++) {
        int idx = t + ii * 256;
        if (idx < 34 * 34) {
            int dy = idx / 34, dx = idx % 34;
            int k = min(max(k0 - 1 + dy, 0), (IMG_H / 2) - 1);
            int l = min(max(l0 - 1 + dx, 0), (IMG_W / 2) - 1);
            sp0[dy][dx] = img[(2 * k) * IMG_W + 2 * l];
            sp3[dy][dx] = img[(2 * k + 1) * IMG_W + 2 * l + 1];
        }
    }
    __syncthreads();

    const float T = 50.0f / 255.0f;
    float accA = 0.0f;      // n2n
    float s1 = 0.0f;        // level-1 wavelet sum

    // ---- 4 register-resident 2x2 quads per thread (2x2 cluster of quads) ----
    const int qqy = t >> 4;   // 0..15
    const int qqx = t & 15;   // 0..15
    #pragma unroll
    for (int q = 0; q < 4; q++) {
        const int qy = qqy * 2 + (q >> 1);   // 0..31
        const int qx = qqx * 2 + (q & 1);    // 0..31
        const int gi0 = ty0 + 2 * qy;
        const int gj0 = tx0 + 2 * qx;

        // p0 3x3 window
        float P00 = sp0[qy    ][qx], P01 = sp0[qy    ][qx + 1], P02 = sp0[qy    ][qx + 2];
        float P10 = sp0[qy + 1][qx], P11 = sp0[qy + 1][qx + 1], P12 = sp0[qy + 1][qx + 2];
        float P20 = sp0[qy + 2][qx], P21 = sp0[qy + 2][qx + 1], P22 = sp0[qy + 2][qx + 2];

        // row-interp g1 rows (gi0-1 .. gi0+2) at the 3 p0 columns
        float RA0 = 0.75f * P00 + 0.25f * P10, RA1 = 0.75f * P01 + 0.25f * P11, RA2 = 0.75f * P02 + 0.25f * P12;
        float RB0 = 0.25f * P00 + 0.75f * P10, RB1 = 0.25f * P01 + 0.75f * P11, RB2 = 0.25f * P02 + 0.75f * P12;
        float RC0 = 0.75f * P10 + 0.25f * P20, RC1 = 0.75f * P11 + 0.25f * P21, RC2 = 0.75f * P12 + 0.25f * P22;
        float RD0 = 0.25f * P10 + 0.75f * P20, RD1 = 0.25f * P11 + 0.75f * P21, RD2 = 0.25f * P12 + 0.75f * P22;

        // conv zero-pad masks (outermost g1 row/col outside image -> 0)
        float mr0 = (gi0 > 0)         ? 1.0f : 0.0f;
        float mr3 = (gi0 + 2 < IMG_H) ? 1.0f : 0.0f;
        float mc0 = (gj0 > 0)         ? 1.0f : 0.0f;
        float mc3 = (gj0 + 2 < IMG_W) ? 1.0f : 0.0f;

        float G[4][4];
        {
            float r0[3] = {RA0, RA1, RA2}, r1[3] = {RB0, RB1, RB2};
            float r2[3] = {RC0, RC1, RC2}, r3[3] = {RD0, RD1, RD2};
            float* rows[4] = {r0, r1, r2, r3};
            #pragma unroll
            for (int r = 0; r < 4; r++) {
                float* R = rows[r];
                G[r][0] = 0.75f * R[0] + 0.25f * R[1];
                G[r][1] = 0.25f * R[0] + 0.75f * R[1];
                G[r][2] = 0.75f * R[1] + 0.25f * R[2];
                G[r][3] = 0.25f * R[1] + 0.75f * R[2];
            }
            #pragma unroll
            for (int c = 0; c < 4; c++) { G[0][c] *= mr0; G[3][c] *= mr3; }
            #pragma unroll
            for (int r = 0; r < 4; r++) { G[r][0] *= mc0; G[r][3] *= mc3; }
        }

        // 3x3 conv + clip
        float o[2][2];
        #pragma unroll
        for (int dy = 0; dy < 2; dy++) {
            #pragma unroll
            for (int dx = 0; dx < 2; dx++) {
                float s = G[dy    ][dx] * w00 + G[dy    ][dx + 1] * w01 + G[dy    ][dx + 2] * w02
                        + G[dy + 1][dx] * w10 + G[dy + 1][dx + 1] * w11 + G[dy + 1][dx + 2] * w12
                        + G[dy + 2][dx] * w20 + G[dy + 2][dx + 1] * w21 + G[dy + 2][dx + 2] * w22;
                o[dy][dx] = fminf(fmaxf(s, 0.0f), 1.0f);
            }
        }

        // g2 quad from p3 3x3 window
        float Q00 = sp3[qy    ][qx], Q01 = sp3[qy    ][qx + 1], Q02 = sp3[qy    ][qx + 2];
        float Q10 = sp3[qy + 1][qx], Q11 = sp3[qy + 1][qx + 1], Q12 = sp3[qy + 1][qx + 2];
        float Q20 = sp3[qy + 2][qx], Q21 = sp3[qy + 2][qx + 1], Q22 = sp3[qy + 2][qx + 2];
        float SA0 = 0.25f * Q00 + 0.75f * Q10, SA1 = 0.25f * Q01 + 0.75f * Q11, SA2 = 0.25f * Q02 + 0.75f * Q12;
        float SB0 = 0.75f * Q10 + 0.25f * Q20, SB1 = 0.75f * Q11 + 0.25f * Q21, SB2 = 0.75f * Q12 + 0.25f * Q22;
        float g2q[2][2];
        g2q[0][0] = 0.25f * SA0 + 0.75f * SA1;  g2q[0][1] = 0.75f * SA1 + 0.25f * SA2;
        g2q[1][0] = 0.25f * SB0 + 0.75f * SB1;  g2q[1][1] = 0.75f * SB1 + 0.25f * SB2;

        // N2N: (out-g2)^2 + 2*(out-g1)^2 ; g1 at quad = G[1+dy][1+dx]
        #pragma unroll
        for (int dy = 0; dy < 2; dy++) {
            #pragma unroll
            for (int dx = 0; dx < 2; dx++) {
                float d1 = o[dy][dx] - g2q[dy][dx];
                float d2 = o[dy][dx] - G[1 + dy][1 + dx];
                accA += d1 * d1 + 2.0f * d2 * d2;
            }
        }

        // Haar level 1 directly from quad
        {
            float a = o[0][0], bb = o[0][1], cc = o[1][0], dd = o[1][1];
            float ll = (a + bb + cc + dd) * 0.5f;
            float lh = (a - bb + cc - dd) * 0.5f;
            float hl = (a + bb - cc - dd) * 0.5f;
            float hh = (a - bb - cc + dd) * 0.5f;
            float thr = T * 0.25f;
            s1 += fminf(fabsf(lh), thr) + fminf(fabsf(hl), thr) + fminf(fabsf(hh), thr);
            sll1[qy][qx] = ll;
        }
    }
    __syncthreads();

    // ---- Haar level 2: 16x16 outputs, one per thread ----
    float s2;
    {
        int r = t >> 4, c = t & 15;
        float a  = sll1[2 * r][2 * c],     bb = sll1[2 * r][2 * c + 1];
        float cc = sll1[2 * r + 1][2 * c], dd = sll1[2 * r + 1][2 * c + 1];
        float ll = (a + bb + cc + dd) * 0.5f;
        float lh = (a - bb + cc - dd) * 0.5f;
        float hl = (a + bb - cc - dd) * 0.5f;
        float hh = (a - bb - cc + dd) * 0.5f;
        float thr = T * 0.5f;
        s2 = fminf(fabsf(lh), thr) + fminf(fabsf(hl), thr) + fminf(fabsf(hh), thr);
        sll2[r][c] = ll;
    }
    __syncthreads();

    // ---- Haar level 3: 8x8 outputs ----
    float s3 = 0.0f;
    if (t < 64) {
        int r = t >> 3, c = t & 7;
        float a  = sll2[2 * r][2 * c],     bb = sll2[2 * r][2 * c + 1];
        float cc = sll2[2 * r + 1][2 * c], dd = sll2[2 * r + 1][2 * c + 1];
        float lh = (a - bb + cc - dd) * 0.5f;
        float hl = (a + bb - cc - dd) * 0.5f;
        float hh = (a - bb - cc + dd) * 0.5f;
        s3 = fminf(fabsf(lh), T) + fminf(fabsf(hl), T) + fminf(fabsf(hh), T);
    }

    // wavelet per-element weights: w_j / (3 * N_j)
    const float c1 = (float)((1.0 / 3.0) / (3.0 * 2097152.0));
    const float c2 = (float)((1.0 / 2.0) / (3.0 * 524288.0));
    const float c3 = (float)(1.0 / (3.0 * 131072.0));
    float mW = c1 * s1 + c2 * s2 + c3 * s3;
    float mA = accA;

    // ---- block reduction ----
    #pragma unroll
    for (int off = 16; off > 0; off >>= 1) {
        mA += __shfl_down_sync(0xffffffff, mA, off);
        mW += __shfl_down_sync(0xffffffff, mW, off);
    }
    int warp = t >> 5, lane = t & 31;
    if (lane == 0) { red[0][warp] = (double)mA; red[1][warp] = (double)mW; }
    __syncthreads();
    if (t == 0) {
        double A = 0.0, Wv = 0.0;
        #pragma unroll
        for (int i = 0; i < 8; i++) { A += red[0][i]; Wv += red[1][i]; }
        int bid = (blockIdx.z * gridDim.y + blockIdx.y) * gridDim.x + blockIdx.x;
        g_part[bid] = make_double2(A, Wv);
        __threadfence();
        unsigned int old = atomicAdd(&g_ticket, 1u);
        isLast = ((old % NBLOCKS) == (NBLOCKS - 1));
    }
    __syncthreads();

    // ---- last block of this launch reduces all partials and writes the scalar ----
    if (isLast) {
        double A = 0.0, Wv = 0.0;
        #pragma unroll
        for (int i = t; i < NBLOCKS; i += 256) {
            double2 p = g_part[i];
            A += p.x; Wv += p.y;
        }
        #pragma unroll
        for (int off = 16; off > 0; off >>= 1) {
            A  += __shfl_down_sync(0xffffffff, A, off);
            Wv += __shfl_down_sync(0xffffffff, Wv, off);
        }
        if (lane == 0) { red[0][warp] = A; red[1][warp] = Wv; }
        __syncthreads();
        if (t == 0) {
            A = 0.0; Wv = 0.0;
            #pragma unroll
            for (int i = 0; i < 8; i++) { A += red[0][i]; Wv += red[1][i]; }
            out[0] = (float)(A / 8388608.0 + 0.05 * Wv);
        }
    }
}

extern "C" void kernel_launch(void* const* d_in, const int* in_sizes, int n_in,
                              void* d_out, int out_size) {
    const float* noisy  = (const float*)d_in[0];
    const float* weight = (const float*)d_in[1];
    float* out = (float*)d_out;

    dim3 grid(IMG_W / TILE, IMG_H / TILE, NBATCH);   // 8 x 8 x 32
    fused_loss_kernel<<<grid, 256>>>(noisy, weight, out);
}

// round 5
// speedup vs baseline: 3.0833x; 1.0593x over previous
#include <cuda_runtime.h>

#define IMG_H 512
#define IMG_W 512
#define NBATCH 32
#define TILE 64
#define NBLOCKS (8 * 8 * 32)   // 2048

// Per-block partial sums: .x = n2n sum, .y = weighted wavelet sum.
__device__ double2 g_part[NBLOCKS];
// Monotonic ticket; (old % NBLOCKS == NBLOCKS-1) identifies last block of this launch.
__device__ unsigned int g_ticket = 0;

__global__ void __launch_bounds__(256) fused_loss_kernel(
    const float* __restrict__ noisy,   // (32,1,512,512)
    const float* __restrict__ weight,  // (1,1,3,3)
    float* __restrict__ out)
{
    const int tx0 = blockIdx.x * TILE;
    const int ty0 = blockIdx.y * TILE;
    const int b   = blockIdx.z;
    const float* img = noisy + (size_t)b * IMG_H * IMG_W;

    __shared__ float sp0[34][36];    // even/even sub-image patch (clamped), halo 1
    __shared__ float sp3[34][36];    // odd/odd sub-image patch (clamped), halo 1
    __shared__ float sll2[16][17];   // Haar level-2 LL
    __shared__ double red[2][8];
    __shared__ bool isLast;

    const int t  = threadIdx.x;
    const int k0 = ty0 >> 1;
    const int l0 = tx0 >> 1;

    const float w00 = __ldg(weight + 0), w01 = __ldg(weight + 1), w02 = __ldg(weight + 2);
    const float w10 = __ldg(weight + 3), w11 = __ldg(weight + 4), w12 = __ldg(weight + 5);
    const float w20 = __ldg(weight + 6), w21 = __ldg(weight + 7), w22 = __ldg(weight + 8);

    // ---- load 34x34 p0/p3 patches (index clamp == jax resize edge renorm) ----
    #pragma unroll
    for (int ii = 0; ii < 5; ii++) {
        int idx = t + ii * 256;
        if (idx < 34 * 34) {
            int dy = idx / 34, dx = idx % 34;
            int k = min(max(k0 - 1 + dy, 0), (IMG_H / 2) - 1);
            int l = min(max(l0 - 1 + dx, 0), (IMG_W / 2) - 1);
            sp0[dy][dx] = img[(2 * k) * IMG_W + 2 * l];
            sp3[dy][dx] = img[(2 * k + 1) * IMG_W + 2 * l + 1];
        }
    }
    __syncthreads();

    // ---- per-thread 4x4 output block ----
    const int qqy = t >> 4;             // 0..15
    const int qqx = t & 15;             // 0..15
    const int py  = 2 * qqy;            // patch row base (p0 row k-1 of block)
    const int px  = 2 * qqx;            // patch col base
    const int gi_base = ty0 + 4 * qqy - 1;   // fine row of g1 row r=0
    const int gj_base = tx0 + 4 * qqx - 1;   // fine col of g1 col cidx=0

    const float mc0 = (gj_base >= 0)        ? 1.0f : 0.0f;
    const float mc5 = (gj_base + 5 < IMG_W) ? 1.0f : 0.0f;

    // Rolling buffer of 3 g1 fine-rows, 6 wide (fine cols gj_base..gj_base+5).
    float gr[3][6];

    // Fill g1 fine-row r into slot s. Fine row gi_base+r; zero-masked outside image.
    #define FILL_ROW(s, r) { \
        const int   pr = (r) >> 1; \
        float wa = ((r) & 1) ? 0.25f : 0.75f; \
        const float m = (gi_base + (r) >= 0 && gi_base + (r) < IMG_H) ? 1.0f : 0.0f; \
        wa *= m; const float wb = m - wa; \
        const float y0 = wa * sp0[py + pr][px + 0] + wb * sp0[py + pr + 1][px + 0]; \
        const float y1 = wa * sp0[py + pr][px + 1] + wb * sp0[py + pr + 1][px + 1]; \
        const float y2 = wa * sp0[py + pr][px + 2] + wb * sp0[py + pr + 1][px + 2]; \
        const float y3 = wa * sp0[py + pr][px + 3] + wb * sp0[py + pr + 1][px + 3]; \
        gr[s][0] = (0.75f * y0 + 0.25f * y1) * mc0; \
        gr[s][1] =  0.25f * y0 + 0.75f * y1; \
        gr[s][2] =  0.75f * y1 + 0.25f * y2; \
        gr[s][3] =  0.25f * y1 + 0.75f * y2; \
        gr[s][4] =  0.75f * y2 + 0.25f * y3; \
        gr[s][5] = (0.25f * y2 + 0.75f * y3) * mc5; \
    }

    FILL_ROW(0, 0)
    FILL_ROW(1, 1)

    const float T = 50.0f / 255.0f;
    float accA = 0.0f;
    float s1 = 0.0f;
    float ll[2][2];
    float obuf[4];

    #pragma unroll
    for (int oy = 0; oy < 4; oy++) {
        FILL_ROW((oy + 2) % 3, oy + 2)
        const int i0 = oy % 3, i1 = (oy + 1) % 3, i2 = (oy + 2) % 3;

        // g2 y-interp for this output row (from p3 patch)
        const int   pr3 = (oy + 1) >> 1;
        const float wa3 = (oy & 1) ? 0.75f : 0.25f;
        const float wb3 = 1.0f - wa3;
        const float z0 = wa3 * sp3[py + pr3][px + 0] + wb3 * sp3[py + pr3 + 1][px + 0];
        const float z1 = wa3 * sp3[py + pr3][px + 1] + wb3 * sp3[py + pr3 + 1][px + 1];
        const float z2 = wa3 * sp3[py + pr3][px + 2] + wb3 * sp3[py + pr3 + 1][px + 2];
        const float z3 = wa3 * sp3[py + pr3][px + 3] + wb3 * sp3[py + pr3 + 1][px + 3];
        const float zv[4] = {z0, z1, z2, z3};

        float orow[4];
        #pragma unroll
        for (int ox = 0; ox < 4; ox++) {
            float s = gr[i0][ox] * w00 + gr[i0][ox + 1] * w01 + gr[i0][ox + 2] * w02
                    + gr[i1][ox] * w10 + gr[i1][ox + 1] * w11 + gr[i1][ox + 2] * w12
                    + gr[i2][ox] * w20 + gr[i2][ox + 1] * w21 + gr[i2][ox + 2] * w22;
            const float o = fminf(fmaxf(s, 0.0f), 1.0f);
            orow[ox] = o;

            const float g1v = gr[i1][ox + 1];
            const int   pc  = (ox + 1) >> 1;
            const float wxa = (ox & 1) ? 0.75f : 0.25f;
            const float g2v = wxa * zv[pc] + (1.0f - wxa) * zv[pc + 1];

            const float d1 = o - g2v;
            const float d2 = o - g1v;
            accA += d1 * d1 + 2.0f * d2 * d2;
        }

        if (oy & 1) {
            // Haar level 1 for the two 2x2 cells of this row pair
            const int ry = oy >> 1;
            #pragma unroll
            for (int cx = 0; cx < 2; cx++) {
                const float a  = obuf[2 * cx],     bb = obuf[2 * cx + 1];
                const float cc = orow[2 * cx],     dd = orow[2 * cx + 1];
                const float l  = (a + bb + cc + dd) * 0.5f;
                const float lh = (a - bb + cc - dd) * 0.5f;
                const float hl = (a + bb - cc - dd) * 0.5f;
                const float hh = (a - bb - cc + dd) * 0.5f;
                const float thr = T * 0.25f;
                s1 += fminf(fabsf(lh), thr) + fminf(fabsf(hl), thr) + fminf(fabsf(hh), thr);
                ll[ry][cx] = l;
            }
        } else {
            obuf[0] = orow[0]; obuf[1] = orow[1]; obuf[2] = orow[2]; obuf[3] = orow[3];
        }
    }
    #undef FILL_ROW

    // ---- Haar level 2 fully in registers (thread's 4x4 block = one L2 cell) ----
    float s2;
    {
        const float a = ll[0][0], bb = ll[0][1], cc = ll[1][0], dd = ll[1][1];
        const float l  = (a + bb + cc + dd) * 0.5f;
        const float lh = (a - bb + cc - dd) * 0.5f;
        const float hl = (a + bb - cc - dd) * 0.5f;
        const float hh = (a - bb - cc + dd) * 0.5f;
        const float thr = T * 0.5f;
        s2 = fminf(fabsf(lh), thr) + fminf(fabsf(hl), thr) + fminf(fabsf(hh), thr);
        sll2[qqy][qqx] = l;
    }
    __syncthreads();

    // ---- Haar level 3: 8x8 outputs ----
    float s3 = 0.0f;
    if (t < 64) {
        const int r = t >> 3, c = t & 7;
        const float a  = sll2[2 * r][2 * c],     bb = sll2[2 * r][2 * c + 1];
        const float cc = sll2[2 * r + 1][2 * c], dd = sll2[2 * r + 1][2 * c + 1];
        const float lh = (a - bb + cc - dd) * 0.5f;
        const float hl = (a + bb - cc - dd) * 0.5f;
        const float hh = (a - bb - cc + dd) * 0.5f;
        s3 = fminf(fabsf(lh), T) + fminf(fabsf(hl), T) + fminf(fabsf(hh), T);
    }

    // wavelet per-element weights: w_j / (3 * N_j)
    const float c1 = (float)((1.0 / 3.0) / (3.0 * 2097152.0));
    const float c2 = (float)((1.0 / 2.0) / (3.0 * 524288.0));
    const float c3 = (float)(1.0 / (3.0 * 131072.0));
    float mW = c1 * s1 + c2 * s2 + c3 * s3;
    float mA = accA;

    // ---- block reduction ----
    #pragma unroll
    for (int off = 16; off > 0; off >>= 1) {
        mA += __shfl_down_sync(0xffffffff, mA, off);
        mW += __shfl_down_sync(0xffffffff, mW, off);
    }
    const int warp = t >> 5, lane = t & 31;
    if (lane == 0) { red[0][warp] = (double)mA; red[1][warp] = (double)mW; }
    __syncthreads();
    if (t == 0) {
        double A = 0.0, Wv = 0.0;
        #pragma unroll
        for (int i = 0; i < 8; i++) { A += red[0][i]; Wv += red[1][i]; }
        const int bid = (blockIdx.z * gridDim.y + blockIdx.y) * gridDim.x + blockIdx.x;
        g_part[bid] = make_double2(A, Wv);
        __threadfence();
        const unsigned int old = atomicAdd(&g_ticket, 1u);
        isLast = ((old % NBLOCKS) == (NBLOCKS - 1));
    }
    __syncthreads();

    // ---- last block reduces all partials and writes the scalar ----
    if (isLast) {
        double A = 0.0, Wv = 0.0;
        #pragma unroll
        for (int i = t; i < NBLOCKS; i += 256) {
            const double2 p = g_part[i];
            A += p.x; Wv += p.y;
        }
        #pragma unroll
        for (int off = 16; off > 0; off >>= 1) {
            A  += __shfl_down_sync(0xffffffff, A, off);
            Wv += __shfl_down_sync(0xffffffff, Wv, off);
        }
        if (lane == 0) { red[0][warp] = A; red[1][warp] = Wv; }
        __syncthreads();
        if (t == 0) {
            A = 0.0; Wv = 0.0;
            #pragma unroll
            for (int i = 0; i < 8; i++) { A += red[0][i]; Wv += red[1][i]; }
            out[0] = (float)(A / 8388608.0 + 0.05 * Wv);
        }
    }
}

extern "C" void kernel_launch(void* const* d_in, const int* in_sizes, int n_in,
                              void* d_out, int out_size) {
    const float* noisy  = (const float*)d_in[0];
    const float* weight = (const float*)d_in[1];
    float* out = (float*)d_out;

    dim3 grid(IMG_W / TILE, IMG_H / TILE, NBATCH);   // 8 x 8 x 32
    fused_loss_kernel<<<grid, 256>>>(noisy, weight, out);
}